// round 6
// baseline (speedup 1.0000x reference)
#include <cuda_runtime.h>
#include <math.h>
#include <stdint.h>

#define DIM 768
#define TOPK 5
#define COS_EPS 1e-8f
#define W_EPS 1e-6f

#define NBLOCKS 1184      // 148 SMs * 8
#define NTHREADS 256      // 8 warps
#define NWARPS (NTHREADS / 32)
#define NWARPS_TOTAL (NBLOCKS * NWARPS)   // 9472
#define NCAND (NBLOCKS * TOPK)            // 5920

// candidate keys: (monotone dist bits << 32) | row index
__device__ unsigned long long g_cand[NCAND];

__device__ __forceinline__ unsigned int f2u_mono(float f) {
    unsigned int b = __float_as_uint(f);
    return b ^ ((unsigned int)(((int)b) >> 31) | 0x80000000u);
}
__device__ __forceinline__ float u2f_mono(unsigned int u) {
    unsigned int b = (u & 0x80000000u) ? (u ^ 0x80000000u) : ~u;
    return __uint_as_float(b);
}

__device__ __forceinline__ void insert5(unsigned long long best[TOPK],
                                        unsigned long long key) {
    if (key < best[TOPK - 1]) {
        best[TOPK - 1] = key;
        #pragma unroll
        for (int k = TOPK - 1; k > 0; k--) {
            if (best[k] < best[k - 1]) {
                unsigned long long t = best[k];
                best[k] = best[k - 1];
                best[k - 1] = t;
            }
        }
    }
}

// Warp-collective: each lane holds a sorted (ascending) top-5; produce the
// warp-wide top-5 into out5 (written by lane 0) by 5 pop-min rounds.
__device__ __forceinline__ void warp_merge5(unsigned long long best[TOPK],
                                            int lane,
                                            unsigned long long* out5) {
    #pragma unroll
    for (int k = 0; k < TOPK; k++) {
        unsigned long long m = best[0];
        #pragma unroll
        for (int o = 16; o; o >>= 1) {
            unsigned long long v = __shfl_xor_sync(0xFFFFFFFFu, m, o);
            if (v < m) m = v;
        }
        unsigned int mask = __ballot_sync(0xFFFFFFFFu, best[0] == m);
        int src = __ffs(mask) - 1;
        if (lane == src) {   // pop: shift up
            #pragma unroll
            for (int j = 0; j < TOPK - 1; j++) best[j] = best[j + 1];
            best[TOPK - 1] = ~0ULL;
        }
        if (lane == 0) out5[k] = m;
    }
}

// ---------------- kernel 1: cosine distance + per-block top-5 ----------------
// Static per-warp contiguous row ranges; per-warp top-5 lives in SHARED
// (lane-0-private, no sync needed) so the hot loop keeps only `worst` in a
// register -> lower reg count -> 6 blocks/SM.
__global__ void __launch_bounds__(NTHREADS, 6)
dist_topk_kernel(const float* __restrict__ db, const float* __restrict__ q, int n) {
    __shared__ __align__(16) float sq[DIM];
    __shared__ float s_wss[NWARPS];
    __shared__ float s_qn;
    __shared__ unsigned long long s_best[NWARPS * TOPK];

    const int tid  = threadIdx.x;
    const int lane = tid & 31;
    const int wid  = tid >> 5;

    // init per-warp top-5 region
    if (tid < NWARPS * TOPK) s_best[tid] = ~0ULL;

    // ---- query load + norm (redundant per block; cheap) ----
    float ss = 0.f;
    for (int i = tid; i < DIM; i += NTHREADS) {
        float v = q[i];
        sq[i] = v;
        ss += v * v;
    }
    #pragma unroll
    for (int o = 16; o; o >>= 1) ss += __shfl_xor_sync(0xFFFFFFFFu, ss, o);
    if (lane == 0) s_wss[wid] = ss;
    __syncthreads();
    if (tid == 0) {
        float t = 0.f;
        #pragma unroll
        for (int i = 0; i < NWARPS; i++) t += s_wss[i];
        s_qn = fmaxf(sqrtf(t), COS_EPS);
    }
    __syncthreads();
    const float qn = s_qn;
    const float4* qv4 = (const float4*)sq;
    unsigned long long* mybest = &s_best[wid * TOPK];

    // contiguous row range for this warp (balanced to +/-1 row)
    const int gwarp = blockIdx.x * NWARPS + wid;
    const int rpw   = (n + NWARPS_TOTAL - 1) / NWARPS_TOTAL;
    const int start = gwarp * rpw;
    const int end   = min(start + rpw, n);

    unsigned long long worst = ~0ULL;   // register copy of mybest[TOPK-1]

    for (int row = start; row < end; row += 2) {
        const bool two = (row + 1 < end);
        const float4* r0 = (const float4*)(db + (size_t)row * DIM);
        const float4* r1 = two ? (const float4*)(db + (size_t)(row + 1) * DIM) : r0;

        float dot0 = 0.f, nrm0 = 0.f, dot1 = 0.f, nrm1 = 0.f;
        #pragma unroll
        for (int j = 0; j < DIM / (32 * 4); j++) {
            float4 a = __ldcs(&r0[lane + 32 * j]);
            float4 b = __ldcs(&r1[lane + 32 * j]);
            float4 qv = qv4[lane + 32 * j];
            dot0 += a.x * qv.x + a.y * qv.y + a.z * qv.z + a.w * qv.w;
            nrm0 += a.x * a.x + a.y * a.y + a.z * a.z + a.w * a.w;
            dot1 += b.x * qv.x + b.y * qv.y + b.z * qv.z + b.w * qv.w;
            nrm1 += b.x * b.x + b.y * b.y + b.z * b.z + b.w * b.w;
        }
        #pragma unroll
        for (int o = 16; o; o >>= 1) {
            dot0 += __shfl_xor_sync(0xFFFFFFFFu, dot0, o);
            nrm0 += __shfl_xor_sync(0xFFFFFFFFu, nrm0, o);
            dot1 += __shfl_xor_sync(0xFFFFFFFFu, dot1, o);
            nrm1 += __shfl_xor_sync(0xFFFFFFFFu, nrm1, o);
        }
        if (lane == 0) {
            float d0 = 1.f - dot0 / (fmaxf(sqrtf(nrm0), COS_EPS) * qn);
            unsigned long long k0 =
                ((unsigned long long)f2u_mono(d0) << 32) | (unsigned int)row;
            if (k0 < worst) {   // rare path: shared-memory sorted insert
                int p = TOPK - 1;
                while (p > 0 && mybest[p - 1] > k0) { mybest[p] = mybest[p - 1]; p--; }
                mybest[p] = k0;
                worst = mybest[TOPK - 1];
            }
            if (two) {
                float d1 = 1.f - dot1 / (fmaxf(sqrtf(nrm1), COS_EPS) * qn);
                unsigned long long k1 =
                    ((unsigned long long)f2u_mono(d1) << 32) | (unsigned int)(row + 1);
                if (k1 < worst) {
                    int p = TOPK - 1;
                    while (p > 0 && mybest[p - 1] > k1) { mybest[p] = mybest[p - 1]; p--; }
                    mybest[p] = k1;
                    worst = mybest[TOPK - 1];
                }
            }
        }
    }
    __syncthreads();

    // ---- per-block merge: 8 warps * 5 -> 5, write to g_cand ----
    if (tid == 0) {
        #pragma unroll
        for (int k = 0; k < TOPK; k++) {
            unsigned long long mn = ~0ULL;
            int mi = 0;
            for (int i = 0; i < NWARPS * TOPK; i++) {
                unsigned long long v = s_best[i];
                if (v < mn) { mn = v; mi = i; }
            }
            g_cand[blockIdx.x * TOPK + k] = mn;
            s_best[mi] = ~0ULL;
        }
    }
}

// ---------------- kernel 2: global top-5 + weighted centroid ----------------
// Single-pass register merge: per-thread insert5 -> warp merge -> warp-0 merge.
__global__ void __launch_bounds__(NTHREADS)
finish_kernel(const float* __restrict__ db, float* __restrict__ out) {
    __shared__ unsigned long long s_cand[NWARPS * TOPK];
    __shared__ unsigned long long s_sel[TOPK];
    __shared__ float s_w[TOPK];
    __shared__ int   s_id[TOPK];

    const int tid  = threadIdx.x;
    const int lane = tid & 31;
    const int wid  = tid >> 5;

    // per-thread top-5 over all candidates (coalesced L2 reads)
    unsigned long long mybest[TOPK];
    #pragma unroll
    for (int k = 0; k < TOPK; k++) mybest[k] = ~0ULL;
    for (int i = tid; i < NCAND; i += NTHREADS)
        insert5(mybest, g_cand[i]);

    // warp merge -> 8*5 in shared
    warp_merge5(mybest, lane, &s_cand[wid * TOPK]);
    __syncthreads();

    // warp 0 merges the 40 survivors
    if (wid == 0) {
        unsigned long long fin[TOPK];
        #pragma unroll
        for (int k = 0; k < TOPK; k++) fin[k] = ~0ULL;
        for (int i = lane; i < NWARPS * TOPK; i += 32)
            insert5(fin, s_cand[i]);
        warp_merge5(fin, lane, s_sel);
    }
    __syncthreads();

    if (tid == 0) {
        float raw[TOPK], s = 0.f;
        #pragma unroll
        for (int k = 0; k < TOPK; k++) {
            float d = u2f_mono((unsigned int)(s_sel[k] >> 32)) + W_EPS;
            raw[k] = 1.f / (d * d);
            s += raw[k];
            s_id[k] = (int)(unsigned int)(s_sel[k] & 0xFFFFFFFFu);
        }
        #pragma unroll
        for (int k = 0; k < TOPK; k++) s_w[k] = raw[k] / s;
    }
    __syncthreads();

    // weighted centroid: 256 threads x 3 dims
    #pragma unroll
    for (int t = 0; t < DIM / NTHREADS; t++) {
        int j = tid + t * NTHREADS;
        float acc = 0.f;
        #pragma unroll
        for (int k = 0; k < TOPK; k++)
            acc += s_w[k] * db[(size_t)s_id[k] * DIM + j];
        out[j] = acc;
    }
}

extern "C" void kernel_launch(void* const* d_in, const int* in_sizes, int n_in,
                              void* d_out, int out_size) {
    const float* q  = (const float*)d_in[0];
    const float* db = (const float*)d_in[1];
    float* out = (float*)d_out;
    const int n = in_sizes[1] / DIM;

    dist_topk_kernel<<<NBLOCKS, NTHREADS>>>(db, q, n);
    finish_kernel<<<1, NTHREADS>>>(db, out);
}

// round 7
// speedup vs baseline: 1.0529x; 1.0529x over previous
#include <cuda_runtime.h>
#include <math.h>
#include <stdint.h>

#define DIM 768
#define TOPK 5
#define COS_EPS 1e-8f
#define W_EPS 1e-6f

#define NBLOCKS 1184      // 148 SMs * 8
#define NTHREADS 256      // 8 warps
#define NWARPS (NTHREADS / 32)

// Global top-5 waterfall slots: monotone-decreasing under atomicMin.
// Static init covers the first run; finish_kernel resets after reading.
__device__ unsigned long long g_top[TOPK] = {~0ULL, ~0ULL, ~0ULL, ~0ULL, ~0ULL};

__device__ __forceinline__ unsigned int f2u_mono(float f) {
    unsigned int b = __float_as_uint(f);
    return b ^ ((unsigned int)(((int)b) >> 31) | 0x80000000u);
}
__device__ __forceinline__ float u2f_mono(unsigned int u) {
    unsigned int b = (u & 0x80000000u) ? (u ^ 0x80000000u) : ~u;
    return __uint_as_float(b);
}

__device__ __forceinline__ void insert5(unsigned long long best[TOPK],
                                        unsigned long long key) {
    if (key < best[TOPK - 1]) {
        best[TOPK - 1] = key;
        #pragma unroll
        for (int k = TOPK - 1; k > 0; k--) {
            if (best[k] < best[k - 1]) {
                unsigned long long t = best[k];
                best[k] = best[k - 1];
                best[k - 1] = t;
            }
        }
    }
}

// Lock-free top-K insert: cascade displaced values down the slots.
// Each slot only ever decreases; the K smallest unique keys always end up
// occupying the K slots (in some order).
__device__ __forceinline__ void waterfall_insert(unsigned long long key) {
    #pragma unroll
    for (int i = 0; i < TOPK; i++) {
        unsigned long long old = atomicMin(&g_top[i], key);
        if (old > key) key = old;   // carry the displaced value onward
    }
}

// ---------------- kernel 1: cosine distance + per-block top-5 ----------------
// R3's measured-best streaming loop (block-contiguous rows, 2 rows/warp iter,
// register-resident sorted top-5, __ldcs). Epilogue: 40->5 block merge, then
// prefiltered atomicMin-waterfall insert into the global top-5.
__global__ void __launch_bounds__(NTHREADS)
dist_topk_kernel(const float* __restrict__ db, const float* __restrict__ q, int n) {
    __shared__ __align__(16) float sq[DIM];
    __shared__ float s_wss[NWARPS];
    __shared__ float s_qn;
    __shared__ unsigned long long s_cand[NWARPS * TOPK];

    const int tid  = threadIdx.x;
    const int lane = tid & 31;
    const int wid  = tid >> 5;

    // query load + norm (redundant per block; cheap)
    float ss = 0.f;
    for (int i = tid; i < DIM; i += NTHREADS) {
        float v = q[i];
        sq[i] = v;
        ss += v * v;
    }
    #pragma unroll
    for (int o = 16; o; o >>= 1) ss += __shfl_xor_sync(0xFFFFFFFFu, ss, o);
    if (lane == 0) s_wss[wid] = ss;
    __syncthreads();
    if (tid == 0) {
        float t = 0.f;
        #pragma unroll
        for (int i = 0; i < NWARPS; i++) t += s_wss[i];
        s_qn = fmaxf(sqrtf(t), COS_EPS);
    }
    __syncthreads();
    const float qn = s_qn;
    const float4* qv4 = (const float4*)sq;

    // contiguous row range for this BLOCK; warps interleaved by 2 rows
    const int rpb    = (n + NBLOCKS - 1) / NBLOCKS;
    const int bstart = blockIdx.x * rpb;
    const int bend   = min(bstart + rpb, n);

    unsigned long long best[TOPK];
    #pragma unroll
    for (int k = 0; k < TOPK; k++) best[k] = ~0ULL;

    for (int row = bstart + wid * 2; row < bend; row += NWARPS * 2) {
        const bool two = (row + 1 < bend);
        const float4* r0 = (const float4*)(db + (size_t)row * DIM);
        const float4* r1 = two ? (const float4*)(db + (size_t)(row + 1) * DIM) : r0;

        float dot0 = 0.f, nrm0 = 0.f, dot1 = 0.f, nrm1 = 0.f;
        #pragma unroll
        for (int j = 0; j < DIM / (32 * 4); j++) {
            float4 a = __ldcs(&r0[lane + 32 * j]);
            float4 b = __ldcs(&r1[lane + 32 * j]);
            float4 qv = qv4[lane + 32 * j];
            dot0 += a.x * qv.x + a.y * qv.y + a.z * qv.z + a.w * qv.w;
            nrm0 += a.x * a.x + a.y * a.y + a.z * a.z + a.w * a.w;
            dot1 += b.x * qv.x + b.y * qv.y + b.z * qv.z + b.w * qv.w;
            nrm1 += b.x * b.x + b.y * b.y + b.z * b.z + b.w * b.w;
        }
        #pragma unroll
        for (int o = 16; o; o >>= 1) {
            dot0 += __shfl_xor_sync(0xFFFFFFFFu, dot0, o);
            nrm0 += __shfl_xor_sync(0xFFFFFFFFu, nrm0, o);
            dot1 += __shfl_xor_sync(0xFFFFFFFFu, dot1, o);
            nrm1 += __shfl_xor_sync(0xFFFFFFFFu, nrm1, o);
        }
        if (lane == 0) {
            float d0 = 1.f - dot0 / (fmaxf(sqrtf(nrm0), COS_EPS) * qn);
            insert5(best, ((unsigned long long)f2u_mono(d0) << 32) | (unsigned int)row);
            if (two) {
                float d1 = 1.f - dot1 / (fmaxf(sqrtf(nrm1), COS_EPS) * qn);
                insert5(best, ((unsigned long long)f2u_mono(d1) << 32) | (unsigned int)(row + 1));
            }
        }
    }

    // per-block merge: 8 warps * 5 -> 5, then waterfall into global top-5
    if (lane == 0) {
        #pragma unroll
        for (int k = 0; k < TOPK; k++) s_cand[wid * TOPK + k] = best[k];
    }
    __syncthreads();
    if (tid == 0) {
        // current 5th-best upper bound; plain load is safe (stale => larger
        // => conservative, extra inserts are harmless)
        unsigned long long thresh = g_top[TOPK - 1];
        #pragma unroll
        for (int k = 0; k < TOPK; k++) {
            unsigned long long mn = ~0ULL;
            int mi = 0;
            for (int i = 0; i < NWARPS * TOPK; i++) {
                unsigned long long v = s_cand[i];
                if (v < mn) { mn = v; mi = i; }
            }
            s_cand[mi] = ~0ULL;
            if (mn < thresh) waterfall_insert(mn);
            else break;   // block candidates sorted ascending: rest can't qualify
        }
    }
}

// ---------------- kernel 2: sort 5 + weights + weighted centroid ----------------
__global__ void __launch_bounds__(DIM)
finish_kernel(const float* __restrict__ db, float* __restrict__ out) {
    __shared__ float s_w[TOPK];
    __shared__ int   s_id[TOPK];

    const int tid = threadIdx.x;

    if (tid == 0) {
        unsigned long long v[TOPK];
        #pragma unroll
        for (int k = 0; k < TOPK; k++) v[k] = g_top[k];
        // sort 5 (slots may be unordered from racing inserts)
        #pragma unroll
        for (int a = 0; a < TOPK; a++)
            #pragma unroll
            for (int b = 0; b < TOPK - 1 - a; b++)
                if (v[b] > v[b + 1]) {
                    unsigned long long t = v[b]; v[b] = v[b + 1]; v[b + 1] = t;
                }
        float raw[TOPK], s = 0.f;
        #pragma unroll
        for (int k = 0; k < TOPK; k++) {
            float d = u2f_mono((unsigned int)(v[k] >> 32)) + W_EPS;
            raw[k] = 1.f / (d * d);
            s += raw[k];
            s_id[k] = (int)(unsigned int)(v[k] & 0xFFFFFFFFu);
        }
        #pragma unroll
        for (int k = 0; k < TOPK; k++) s_w[k] = raw[k] / s;
        // reset waterfall for next graph replay
        #pragma unroll
        for (int k = 0; k < TOPK; k++) g_top[k] = ~0ULL;
    }
    __syncthreads();

    float acc = 0.f;
    #pragma unroll
    for (int k = 0; k < TOPK; k++)
        acc += s_w[k] * db[(size_t)s_id[k] * DIM + tid];
    out[tid] = acc;
}

extern "C" void kernel_launch(void* const* d_in, const int* in_sizes, int n_in,
                              void* d_out, int out_size) {
    const float* q  = (const float*)d_in[0];
    const float* db = (const float*)d_in[1];
    float* out = (float*)d_out;
    const int n = in_sizes[1] / DIM;

    dist_topk_kernel<<<NBLOCKS, NTHREADS>>>(db, q, n);
    finish_kernel<<<1, DIM>>>(db, out);
}

// round 8
// speedup vs baseline: 1.1354x; 1.0783x over previous
#include <cuda_runtime.h>
#include <math.h>
#include <stdint.h>

#define DIM 768
#define TOPK 5
#define COS_EPS 1e-8f
#define W_EPS 1e-6f

#define NBLOCKS 1184      // 148 SMs * 8
#define NTHREADS 256      // 8 warps
#define NWARPS (NTHREADS / 32)
#define NCAND (NBLOCKS * TOPK)   // 5920

#define FTHREADS 1024
#define FWARPS (FTHREADS / 32)   // 32

// candidate keys: (monotone dist bits << 32) | row index
__device__ unsigned long long g_cand[NCAND];

__device__ __forceinline__ unsigned int f2u_mono(float f) {
    unsigned int b = __float_as_uint(f);
    return b ^ ((unsigned int)(((int)b) >> 31) | 0x80000000u);
}
__device__ __forceinline__ float u2f_mono(unsigned int u) {
    unsigned int b = (u & 0x80000000u) ? (u ^ 0x80000000u) : ~u;
    return __uint_as_float(b);
}

__device__ __forceinline__ void insert5(unsigned long long best[TOPK],
                                        unsigned long long key) {
    if (key < best[TOPK - 1]) {
        best[TOPK - 1] = key;
        #pragma unroll
        for (int k = TOPK - 1; k > 0; k--) {
            if (best[k] < best[k - 1]) {
                unsigned long long t = best[k];
                best[k] = best[k - 1];
                best[k - 1] = t;
            }
        }
    }
}

// Warp-collective: each lane holds a sorted (ascending) top-5; produce the
// warp-wide top-5 into out5 (written by lane 0) by 5 pop-min rounds.
__device__ __forceinline__ void warp_merge5(unsigned long long best[TOPK],
                                            int lane,
                                            unsigned long long* out5) {
    #pragma unroll
    for (int k = 0; k < TOPK; k++) {
        unsigned long long m = best[0];
        #pragma unroll
        for (int o = 16; o; o >>= 1) {
            unsigned long long v = __shfl_xor_sync(0xFFFFFFFFu, m, o);
            if (v < m) m = v;
        }
        unsigned int mask = __ballot_sync(0xFFFFFFFFu, best[0] == m);
        int src = __ffs(mask) - 1;
        if (lane == src) {   // pop: shift up
            #pragma unroll
            for (int j = 0; j < TOPK - 1; j++) best[j] = best[j + 1];
            best[TOPK - 1] = ~0ULL;
        }
        if (lane == 0) out5[k] = m;
    }
}

// ---------------- kernel 1: cosine distance + per-block top-5 ----------------
// EXACT R3 structure (measured-best): block-contiguous rows, 2 rows/warp iter,
// register-resident sorted top-5, __ldcs streaming loads, plain g_cand stores.
__global__ void __launch_bounds__(NTHREADS)
dist_topk_kernel(const float* __restrict__ db, const float* __restrict__ q, int n) {
    __shared__ __align__(16) float sq[DIM];
    __shared__ float s_wss[NWARPS];
    __shared__ float s_qn;
    __shared__ unsigned long long s_cand[NWARPS * TOPK];

    const int tid  = threadIdx.x;
    const int lane = tid & 31;
    const int wid  = tid >> 5;

    // query load + norm (redundant per block; cheap)
    float ss = 0.f;
    for (int i = tid; i < DIM; i += NTHREADS) {
        float v = q[i];
        sq[i] = v;
        ss += v * v;
    }
    #pragma unroll
    for (int o = 16; o; o >>= 1) ss += __shfl_xor_sync(0xFFFFFFFFu, ss, o);
    if (lane == 0) s_wss[wid] = ss;
    __syncthreads();
    if (tid == 0) {
        float t = 0.f;
        #pragma unroll
        for (int i = 0; i < NWARPS; i++) t += s_wss[i];
        s_qn = fmaxf(sqrtf(t), COS_EPS);
    }
    __syncthreads();
    const float qn = s_qn;
    const float4* qv4 = (const float4*)sq;

    // contiguous row range for this BLOCK; warps interleaved by 2 rows
    const int rpb    = (n + NBLOCKS - 1) / NBLOCKS;
    const int bstart = blockIdx.x * rpb;
    const int bend   = min(bstart + rpb, n);

    unsigned long long best[TOPK];
    #pragma unroll
    for (int k = 0; k < TOPK; k++) best[k] = ~0ULL;

    for (int row = bstart + wid * 2; row < bend; row += NWARPS * 2) {
        const bool two = (row + 1 < bend);
        const float4* r0 = (const float4*)(db + (size_t)row * DIM);
        const float4* r1 = two ? (const float4*)(db + (size_t)(row + 1) * DIM) : r0;

        float dot0 = 0.f, nrm0 = 0.f, dot1 = 0.f, nrm1 = 0.f;
        #pragma unroll
        for (int j = 0; j < DIM / (32 * 4); j++) {
            float4 a = __ldcs(&r0[lane + 32 * j]);
            float4 b = __ldcs(&r1[lane + 32 * j]);
            float4 qv = qv4[lane + 32 * j];
            dot0 += a.x * qv.x + a.y * qv.y + a.z * qv.z + a.w * qv.w;
            nrm0 += a.x * a.x + a.y * a.y + a.z * a.z + a.w * a.w;
            dot1 += b.x * qv.x + b.y * qv.y + b.z * qv.z + b.w * qv.w;
            nrm1 += b.x * b.x + b.y * b.y + b.z * b.z + b.w * b.w;
        }
        #pragma unroll
        for (int o = 16; o; o >>= 1) {
            dot0 += __shfl_xor_sync(0xFFFFFFFFu, dot0, o);
            nrm0 += __shfl_xor_sync(0xFFFFFFFFu, nrm0, o);
            dot1 += __shfl_xor_sync(0xFFFFFFFFu, dot1, o);
            nrm1 += __shfl_xor_sync(0xFFFFFFFFu, nrm1, o);
        }
        if (lane == 0) {
            float d0 = 1.f - dot0 / (fmaxf(sqrtf(nrm0), COS_EPS) * qn);
            insert5(best, ((unsigned long long)f2u_mono(d0) << 32) | (unsigned int)row);
            if (two) {
                float d1 = 1.f - dot1 / (fmaxf(sqrtf(nrm1), COS_EPS) * qn);
                insert5(best, ((unsigned long long)f2u_mono(d1) << 32) | (unsigned int)(row + 1));
            }
        }
    }

    // block merge: 8 warps * 5 keys -> 5 keys
    if (lane == 0) {
        #pragma unroll
        for (int k = 0; k < TOPK; k++) s_cand[wid * TOPK + k] = best[k];
    }
    __syncthreads();
    if (tid == 0) {
        #pragma unroll
        for (int k = 0; k < TOPK; k++) {
            unsigned long long mn = ~0ULL;
            int mi = 0;
            for (int i = 0; i < NWARPS * TOPK; i++) {
                unsigned long long v = s_cand[i];
                if (v < mn) { mn = v; mi = i; }
            }
            g_cand[blockIdx.x * TOPK + k] = mn;
            s_cand[mi] = ~0ULL;
        }
    }
}

// ---------------- kernel 2: global top-5 + weighted centroid ----------------
// 1024 threads, single-pass hierarchical register merge (~6 keys/thread).
__global__ void __launch_bounds__(FTHREADS)
finish_kernel(const float* __restrict__ db, float* __restrict__ out) {
    __shared__ unsigned long long s_cand[FWARPS * TOPK];  // 160 keys
    __shared__ unsigned long long s_sel[TOPK];
    __shared__ float s_w[TOPK];
    __shared__ int   s_id[TOPK];

    const int tid  = threadIdx.x;
    const int lane = tid & 31;
    const int wid  = tid >> 5;

    // per-thread top-5 over ~6 candidates (coalesced L2 reads)
    unsigned long long mybest[TOPK];
    #pragma unroll
    for (int k = 0; k < TOPK; k++) mybest[k] = ~0ULL;
    #pragma unroll
    for (int r = 0; r < (NCAND + FTHREADS - 1) / FTHREADS; r++) {
        int i = tid + r * FTHREADS;
        if (i < NCAND) insert5(mybest, __ldcg(&g_cand[i]));
    }

    // 32 warp merges -> 160 keys in shared
    warp_merge5(mybest, lane, &s_cand[wid * TOPK]);
    __syncthreads();

    // warp 0 merges the 160 survivors (5 keys per lane)
    if (wid == 0) {
        unsigned long long fin[TOPK];
        #pragma unroll
        for (int k = 0; k < TOPK; k++) fin[k] = ~0ULL;
        #pragma unroll
        for (int r = 0; r < TOPK; r++)
            insert5(fin, s_cand[lane + r * 32]);
        warp_merge5(fin, lane, s_sel);
    }
    __syncthreads();

    if (tid == 0) {
        float raw[TOPK], s = 0.f;
        #pragma unroll
        for (int k = 0; k < TOPK; k++) {
            float d = u2f_mono((unsigned int)(s_sel[k] >> 32)) + W_EPS;
            raw[k] = 1.f / (d * d);
            s += raw[k];
            s_id[k] = (int)(unsigned int)(s_sel[k] & 0xFFFFFFFFu);
        }
        #pragma unroll
        for (int k = 0; k < TOPK; k++) s_w[k] = raw[k] / s;
    }
    __syncthreads();

    // weighted centroid on the first 768 threads
    if (tid < DIM) {
        float acc = 0.f;
        #pragma unroll
        for (int k = 0; k < TOPK; k++)
            acc += s_w[k] * db[(size_t)s_id[k] * DIM + tid];
        out[tid] = acc;
    }
}

extern "C" void kernel_launch(void* const* d_in, const int* in_sizes, int n_in,
                              void* d_out, int out_size) {
    const float* q  = (const float*)d_in[0];
    const float* db = (const float*)d_in[1];
    float* out = (float*)d_out;
    const int n = in_sizes[1] / DIM;

    dist_topk_kernel<<<NBLOCKS, NTHREADS>>>(db, q, n);
    finish_kernel<<<1, FTHREADS>>>(db, out);
}

// round 9
// speedup vs baseline: 1.1503x; 1.0132x over previous
#include <cuda_runtime.h>
#include <math.h>
#include <stdint.h>

#define DIM 768
#define TOPK 5
#define COS_EPS 1e-8f
#define W_EPS 1e-6f

#define NBLOCKS 1184      // 148 SMs * 8
#define NTHREADS 256      // 8 warps
#define NWARPS (NTHREADS / 32)
#define NCAND (NBLOCKS * TOPK)   // 5920

#define FTHREADS 1024
#define FWARPS (FTHREADS / 32)   // 32
#define FROUNDS ((NCAND + FTHREADS - 1) / FTHREADS)  // 6

// candidate keys: (monotone dist bits << 32) | row index
__device__ unsigned long long g_cand[NCAND];

__device__ __forceinline__ unsigned int f2u_mono(float f) {
    unsigned int b = __float_as_uint(f);
    return b ^ ((unsigned int)(((int)b) >> 31) | 0x80000000u);
}
__device__ __forceinline__ float u2f_mono(unsigned int u) {
    unsigned int b = (u & 0x80000000u) ? (u ^ 0x80000000u) : ~u;
    return __uint_as_float(b);
}

__device__ __forceinline__ void insert5(unsigned long long best[TOPK],
                                        unsigned long long key) {
    if (key < best[TOPK - 1]) {
        best[TOPK - 1] = key;
        #pragma unroll
        for (int k = TOPK - 1; k > 0; k--) {
            if (best[k] < best[k - 1]) {
                unsigned long long t = best[k];
                best[k] = best[k - 1];
                best[k - 1] = t;
            }
        }
    }
}

// Warp-collective: each lane holds a sorted (ascending) top-5; produce the
// warp-wide top-5 into out5 (written by lane 0) by 5 pop-min rounds.
__device__ __forceinline__ void warp_merge5(unsigned long long best[TOPK],
                                            int lane,
                                            unsigned long long* out5) {
    #pragma unroll
    for (int k = 0; k < TOPK; k++) {
        unsigned long long m = best[0];
        #pragma unroll
        for (int o = 16; o; o >>= 1) {
            unsigned long long v = __shfl_xor_sync(0xFFFFFFFFu, m, o);
            if (v < m) m = v;
        }
        unsigned int mask = __ballot_sync(0xFFFFFFFFu, best[0] == m);
        int src = __ffs(mask) - 1;
        if (lane == src) {   // pop: shift up
            #pragma unroll
            for (int j = 0; j < TOPK - 1; j++) best[j] = best[j + 1];
            best[TOPK - 1] = ~0ULL;
        }
        if (lane == 0) out5[k] = m;
    }
}

// ---------------- kernel 1: cosine distance + per-block top-5 ----------------
// FROZEN (measured-best across R3..R8): block-contiguous rows, 2 rows/warp
// iter, register-resident sorted top-5, __ldcs streaming, plain g_cand stores.
__global__ void __launch_bounds__(NTHREADS)
dist_topk_kernel(const float* __restrict__ db, const float* __restrict__ q, int n) {
    __shared__ __align__(16) float sq[DIM];
    __shared__ float s_wss[NWARPS];
    __shared__ float s_qn;
    __shared__ unsigned long long s_cand[NWARPS * TOPK];

    const int tid  = threadIdx.x;
    const int lane = tid & 31;
    const int wid  = tid >> 5;

    // query load + norm (redundant per block; cheap)
    float ss = 0.f;
    for (int i = tid; i < DIM; i += NTHREADS) {
        float v = q[i];
        sq[i] = v;
        ss += v * v;
    }
    #pragma unroll
    for (int o = 16; o; o >>= 1) ss += __shfl_xor_sync(0xFFFFFFFFu, ss, o);
    if (lane == 0) s_wss[wid] = ss;
    __syncthreads();
    if (tid == 0) {
        float t = 0.f;
        #pragma unroll
        for (int i = 0; i < NWARPS; i++) t += s_wss[i];
        s_qn = fmaxf(sqrtf(t), COS_EPS);
    }
    __syncthreads();
    const float qn = s_qn;
    const float4* qv4 = (const float4*)sq;

    // contiguous row range for this BLOCK; warps interleaved by 2 rows
    const int rpb    = (n + NBLOCKS - 1) / NBLOCKS;
    const int bstart = blockIdx.x * rpb;
    const int bend   = min(bstart + rpb, n);

    unsigned long long best[TOPK];
    #pragma unroll
    for (int k = 0; k < TOPK; k++) best[k] = ~0ULL;

    for (int row = bstart + wid * 2; row < bend; row += NWARPS * 2) {
        const bool two = (row + 1 < bend);
        const float4* r0 = (const float4*)(db + (size_t)row * DIM);
        const float4* r1 = two ? (const float4*)(db + (size_t)(row + 1) * DIM) : r0;

        float dot0 = 0.f, nrm0 = 0.f, dot1 = 0.f, nrm1 = 0.f;
        #pragma unroll
        for (int j = 0; j < DIM / (32 * 4); j++) {
            float4 a = __ldcs(&r0[lane + 32 * j]);
            float4 b = __ldcs(&r1[lane + 32 * j]);
            float4 qv = qv4[lane + 32 * j];
            dot0 += a.x * qv.x + a.y * qv.y + a.z * qv.z + a.w * qv.w;
            nrm0 += a.x * a.x + a.y * a.y + a.z * a.z + a.w * a.w;
            dot1 += b.x * qv.x + b.y * qv.y + b.z * qv.z + b.w * qv.w;
            nrm1 += b.x * b.x + b.y * b.y + b.z * b.z + b.w * b.w;
        }
        #pragma unroll
        for (int o = 16; o; o >>= 1) {
            dot0 += __shfl_xor_sync(0xFFFFFFFFu, dot0, o);
            nrm0 += __shfl_xor_sync(0xFFFFFFFFu, nrm0, o);
            dot1 += __shfl_xor_sync(0xFFFFFFFFu, dot1, o);
            nrm1 += __shfl_xor_sync(0xFFFFFFFFu, nrm1, o);
        }
        if (lane == 0) {
            float d0 = 1.f - dot0 / (fmaxf(sqrtf(nrm0), COS_EPS) * qn);
            insert5(best, ((unsigned long long)f2u_mono(d0) << 32) | (unsigned int)row);
            if (two) {
                float d1 = 1.f - dot1 / (fmaxf(sqrtf(nrm1), COS_EPS) * qn);
                insert5(best, ((unsigned long long)f2u_mono(d1) << 32) | (unsigned int)(row + 1));
            }
        }
    }

    // block merge: 8 warps * 5 keys -> 5 keys
    if (lane == 0) {
        #pragma unroll
        for (int k = 0; k < TOPK; k++) s_cand[wid * TOPK + k] = best[k];
    }
    __syncthreads();
    if (tid == 0) {
        #pragma unroll
        for (int k = 0; k < TOPK; k++) {
            unsigned long long mn = ~0ULL;
            int mi = 0;
            for (int i = 0; i < NWARPS * TOPK; i++) {
                unsigned long long v = s_cand[i];
                if (v < mn) { mn = v; mi = i; }
            }
            g_cand[blockIdx.x * TOPK + k] = mn;
            s_cand[mi] = ~0ULL;
        }
    }
}

// ---------------- kernel 2: global top-5 + weighted centroid ----------------
// 1024 threads; BATCHED candidate loads (6 independent LDGs in flight) before
// the sequential inserts, then hierarchical register merge.
__global__ void __launch_bounds__(FTHREADS)
finish_kernel(const float* __restrict__ db, float* __restrict__ out) {
    __shared__ unsigned long long s_cand[FWARPS * TOPK];  // 160 keys
    __shared__ unsigned long long s_sel[TOPK];
    __shared__ float s_w[TOPK];
    __shared__ int   s_id[TOPK];

    const int tid  = threadIdx.x;
    const int lane = tid & 31;
    const int wid  = tid >> 5;

    // batch all candidate loads first: 6 independent L2 reads in flight
    unsigned long long keys[FROUNDS];
    #pragma unroll
    for (int r = 0; r < FROUNDS; r++) {
        int i = tid + r * FTHREADS;
        keys[r] = (i < NCAND) ? __ldcg(&g_cand[i]) : ~0ULL;
    }

    unsigned long long mybest[TOPK];
    #pragma unroll
    for (int k = 0; k < TOPK; k++) mybest[k] = ~0ULL;
    #pragma unroll
    for (int r = 0; r < FROUNDS; r++) insert5(mybest, keys[r]);

    // 32 warp merges -> 160 keys in shared
    warp_merge5(mybest, lane, &s_cand[wid * TOPK]);
    __syncthreads();

    // warp 0 merges the 160 survivors (5 keys per lane, loads batched)
    if (wid == 0) {
        unsigned long long lk[TOPK];
        #pragma unroll
        for (int r = 0; r < TOPK; r++) lk[r] = s_cand[lane + r * 32];
        unsigned long long fin[TOPK];
        #pragma unroll
        for (int k = 0; k < TOPK; k++) fin[k] = ~0ULL;
        #pragma unroll
        for (int r = 0; r < TOPK; r++) insert5(fin, lk[r]);
        warp_merge5(fin, lane, s_sel);
    }
    __syncthreads();

    if (tid == 0) {
        float raw[TOPK], s = 0.f;
        #pragma unroll
        for (int k = 0; k < TOPK; k++) {
            float d = u2f_mono((unsigned int)(s_sel[k] >> 32)) + W_EPS;
            raw[k] = 1.f / (d * d);
            s += raw[k];
            s_id[k] = (int)(unsigned int)(s_sel[k] & 0xFFFFFFFFu);
        }
        #pragma unroll
        for (int k = 0; k < TOPK; k++) s_w[k] = raw[k] / s;
    }
    __syncthreads();

    // weighted centroid on the first 768 threads
    if (tid < DIM) {
        float acc = 0.f;
        #pragma unroll
        for (int k = 0; k < TOPK; k++)
            acc += s_w[k] * db[(size_t)s_id[k] * DIM + tid];
        out[tid] = acc;
    }
}

extern "C" void kernel_launch(void* const* d_in, const int* in_sizes, int n_in,
                              void* d_out, int out_size) {
    const float* q  = (const float*)d_in[0];
    const float* db = (const float*)d_in[1];
    float* out = (float*)d_out;
    const int n = in_sizes[1] / DIM;

    dist_topk_kernel<<<NBLOCKS, NTHREADS>>>(db, q, n);
    finish_kernel<<<1, FTHREADS>>>(db, out);
}